// round 6
// baseline (speedup 1.0000x reference)
#include <cuda_runtime.h>
#include <math_constants.h>

// Problem constants (match reference setup_inputs)
#define NROWS 131072
#define D     128
#define NC    512

// Tiling
#define R_TILE   64          // rows per CTA
#define CHUNK    64          // codebook rows per smem chunk
#define THREADS  512

#define XS_STRIDE 130        // 128 + 2 pad (even, conflict-free for LDS.64)
#define CS_STRIDE 130
#define L_STRIDE  516        // 512 + 4 pad (multiple of 4 -> float4-aligned rows)

#define SMEM_FLOATS (2 * R_TILE * XS_STRIDE + R_TILE * L_STRIDE)  // 49664
#define SMEM_BYTES  (SMEM_FLOATS * 4)                              // 198656

#define ARG_MARGIN 1e-5f

__device__ __forceinline__ void fma2(unsigned long long& acc,
                                     unsigned long long a,
                                     unsigned long long b) {
    asm("fma.rn.f32x2 %0, %1, %2, %0;" : "+l"(acc) : "l"(a), "l"(b));
}

__device__ __forceinline__ unsigned long long dup2(float v) {
    unsigned long long r;
    asm("mov.b64 %0, {%1, %1};" : "=l"(r) : "f"(v));
    return r;
}

__device__ __forceinline__ float2 unpack2(unsigned long long v) {
    float2 r;
    asm("mov.b64 {%0, %1}, %2;" : "=f"(r.x), "=f"(r.y) : "l"(v));
    return r;
}

__global__ void __launch_bounds__(THREADS)
gumbel_vq_kernel(const float* __restrict__ x,
                 const float* __restrict__ mask,
                 const float* __restrict__ codebook,
                 const float* __restrict__ noise,
                 float* __restrict__ out_q,    // (n, 128)
                 float* __restrict__ out_e,    // (n, 512)
                 float* __restrict__ out_i)    // (n,) indices as float
{
    extern __shared__ float sm[];
    float* xs = sm;                                  // [R_TILE][XS_STRIDE]
    float* cs = sm + R_TILE * XS_STRIDE;             // [CHUNK][CS_STRIDE]
    float* L  = sm + 2 * R_TILE * XS_STRIDE;         // [R_TILE][L_STRIDE]

    const int t    = threadIdx.x;
    const int row0 = blockIdx.x * R_TILE;

    // ---------------- Load x tile (with mask nudge) ----------------
    for (int f = t; f < R_TILE * D / 4; f += THREADS) {
        int r  = f >> 5;               // 32 float4 per row
        int c4 = (f & 31) << 2;
        float4 v = *reinterpret_cast<const float4*>(x + (size_t)(row0 + r) * D + c4);
        float nud = (1.0f - mask[row0 + r]) * 1e-6f;
        v.x += nud; v.y += nud; v.z += nud; v.w += nud;
        float* dst = xs + r * XS_STRIDE + c4;
        *reinterpret_cast<float2*>(dst)     = make_float2(v.x, v.y);
        *reinterpret_cast<float2*>(dst + 2) = make_float2(v.z, v.w);
    }
    __syncthreads();

    // ---------------- Row normalize (8 threads / row) ----------------
    // fp64 sumsq -> fp32 norm -> elementwise IEEE fp32 division (matches ref).
    {
        int r = t >> 3, q = t & 7;
        float* xr = xs + r * XS_STRIDE + q * 16;
        double s = 0.0;
        #pragma unroll
        for (int k = 0; k < 16; k++) { double v = (double)xr[k]; s += v * v; }
        s += __shfl_xor_sync(0xFFFFFFFFu, s, 1);
        s += __shfl_xor_sync(0xFFFFFFFFu, s, 2);
        s += __shfl_xor_sync(0xFFFFFFFFu, s, 4);
        float nf = (float)sqrt(s);
        nf = fmaxf(nf, 1e-6f);
        #pragma unroll
        for (int k = 0; k < 16; k++) xr[k] = xr[k] / nf;   // IEEE fp32 div
    }
    __syncthreads();

    const int ty = t >> 4;   // 0..31 (row groups of 2)
    const int tx = t & 15;   // 0..15

    // ---------------- GEMM1: ab = xn @ C^T, write to L ----------------
    // thread tile: 2 rows x 4 codes (codes tx + 16j)
    for (int cb = 0; cb < NC; cb += CHUNK) {
        for (int f = t; f < CHUNK * D / 4; f += THREADS) {
            int r  = f >> 5;
            int c4 = (f & 31) << 2;
            float4 v = *reinterpret_cast<const float4*>(codebook + (size_t)(cb + r) * D + c4);
            float* dst = cs + r * CS_STRIDE + c4;
            *reinterpret_cast<float2*>(dst)     = make_float2(v.x, v.y);
            *reinterpret_cast<float2*>(dst + 2) = make_float2(v.z, v.w);
        }
        __syncthreads();

        unsigned long long acc[2][4];
        #pragma unroll
        for (int i = 0; i < 2; i++)
            #pragma unroll
            for (int j = 0; j < 4; j++) acc[i][j] = 0ull;

        const float* xb  = xs + (2 * ty) * XS_STRIDE;
        const float* cbp = cs + tx * CS_STRIDE;

        #pragma unroll 8
        for (int k2 = 0; k2 < 64; k2++) {
            unsigned long long a2[2], b2[4];
            #pragma unroll
            for (int i = 0; i < 2; i++)
                a2[i] = *reinterpret_cast<const unsigned long long*>(xb + i * XS_STRIDE + 2 * k2);
            #pragma unroll
            for (int j = 0; j < 4; j++)
                b2[j] = *reinterpret_cast<const unsigned long long*>(cbp + 16 * j * CS_STRIDE + 2 * k2);
            #pragma unroll
            for (int i = 0; i < 2; i++)
                #pragma unroll
                for (int j = 0; j < 4; j++)
                    fma2(acc[i][j], a2[i], b2[j]);
        }

        #pragma unroll
        for (int i = 0; i < 2; i++) {
            #pragma unroll
            for (int j = 0; j < 4; j++) {
                float2 p = unpack2(acc[i][j]);
                L[(2 * ty + i) * L_STRIDE + cb + tx + 16 * j] = p.x + p.y;
            }
        }
        __syncthreads();
    }

    // ---------------- Argmin + Softmax, register-resident (8 threads / row) ----
    {
        int r = t >> 3, g = t & 7;
        const int gr = row0 + r;
        float* Lr = L + r * L_STRIDE;
        const float* nzr = noise + (size_t)gr * NC;

        // interleaved float4 ownership: thread g owns float4 blocks (kk*8+g), kk=0..15
        float v[64];
        float vmax = -CUDART_INF_F;
        float m1 = -CUDART_INF_F, m2 = -CUDART_INF_F;
        int i1 = 1 << 30;

        #pragma unroll
        for (int kk = 0; kk < 16; kk++) {
            int c4 = (kk * 8 + g) * 4;
            float4 ab4 = *reinterpret_cast<const float4*>(Lr + c4);
            float4 nv  = *reinterpret_cast<const float4*>(nzr + c4);
            float ab[4] = {ab4.x, ab4.y, ab4.z, ab4.w};
            float nn[4] = {nv.x,  nv.y,  nv.z,  nv.w};
            #pragma unroll
            for (int jj = 0; jj < 4; jj++) {
                float a = ab[jj];
                float lv = 2.0f * a + nn[jj];
                v[kk * 4 + jj] = lv;
                vmax = fmaxf(vmax, lv);
                if (a > m1) { m2 = m1; m1 = a; i1 = c4 + jj; }
                else        { m2 = fmaxf(m2, a); }
            }
        }

        // reduce across the 8 lanes of this row
        #pragma unroll
        for (int dlt = 1; dlt <= 4; dlt <<= 1) {
            vmax = fmaxf(vmax, __shfl_xor_sync(0xFFFFFFFFu, vmax, dlt));
            float om1 = __shfl_xor_sync(0xFFFFFFFFu, m1, dlt);
            float om2 = __shfl_xor_sync(0xFFFFFFFFu, m2, dlt);
            int   oi1 = __shfl_xor_sync(0xFFFFFFFFu, i1, dlt);
            if (om1 > m1)       { m2 = fmaxf(m1, om2); m1 = om1; i1 = oi1; }
            else if (om1 == m1) { m2 = m1; i1 = min(i1, oi1); }
            else                { m2 = fmaxf(m2, om1); }
        }

        int final_idx = i1;
        if (!(m1 - m2 > ARG_MARGIN)) {
            // tier 2: replicate reference arithmetic on near-max candidates:
            // serial ascending-k fp32 FMA dot, then d = (1 - 2*ab) + 1,
            // argmin with first-index tie-break. L still holds ab here.
            unsigned sub = 0xFFu << ((t & 31) & ~7);   // this row's 8 lanes
            const float* xr = xs + r * XS_STRIDE;
            float bd = CUDART_INF_F;
            int bi = 1 << 30;
            float thresh = m1 - ARG_MARGIN;
            for (int kk = 0; kk < 16; kk++) {
                int c4 = (kk * 8 + g) * 4;
                #pragma unroll
                for (int jj = 0; jj < 4; jj++) {
                    if (Lr[c4 + jj] >= thresh) {
                        const float* cj = codebook + (size_t)(c4 + jj) * D;
                        float acc = 0.0f;
                        #pragma unroll 8
                        for (int kd = 0; kd < 128; kd++)
                            acc = fmaf(xr[kd], cj[kd], acc);   // serial ascending k
                        float df = (1.0f - 2.0f * acc) + 1.0f;
                        int ci = c4 + jj;
                        if (df < bd || (df == bd && ci < bi)) { bd = df; bi = ci; }
                    }
                }
            }
            #pragma unroll
            for (int dlt = 1; dlt <= 4; dlt <<= 1) {
                float od = __shfl_xor_sync(sub, bd, dlt);
                int   oi = __shfl_xor_sync(sub, bi, dlt);
                if (od < bd || (od == bd && oi < bi)) { bd = od; bi = oi; }
            }
            final_idx = bi;
        }
        if (g == 0) out_i[gr] = (float)final_idx;

        // exp + sum (registers)
        float s = 0.f;
        #pragma unroll
        for (int k = 0; k < 64; k++) {
            float e = __expf(v[k] - vmax);
            v[k] = e;
            s += e;
        }
        s += __shfl_xor_sync(0xFFFFFFFFu, s, 1);
        s += __shfl_xor_sync(0xFFFFFFFFu, s, 2);
        s += __shfl_xor_sync(0xFFFFFFFFu, s, 4);
        float inv = 1.0f / s;

        // normalize, write encodings to smem (for GEMM2) and global
        float* ez = out_e + (size_t)gr * NC;
        #pragma unroll
        for (int kk = 0; kk < 16; kk++) {
            int c4 = (kk * 8 + g) * 4;
            float4 ev;
            ev.x = v[kk * 4 + 0] * inv;
            ev.y = v[kk * 4 + 1] * inv;
            ev.z = v[kk * 4 + 2] * inv;
            ev.w = v[kk * 4 + 3] * inv;
            *reinterpret_cast<float4*>(Lr + c4) = ev;
            *reinterpret_cast<float4*>(ez + c4) = ev;
        }
    }

    // ---------------- GEMM2: quantized = enc @ C ----------------
    // thread tile: 2 rows x 4 f32x2 d-col pairs (cols 2tx + 32j)
    unsigned long long qa[2][4];
    #pragma unroll
    for (int i = 0; i < 2; i++)
        #pragma unroll
        for (int j = 0; j < 4; j++) qa[i][j] = 0ull;

    for (int cb = 0; cb < NC; cb += CHUNK) {
        __syncthreads();   // softmax L writes done / prev chunk consumers done
        for (int f = t; f < CHUNK * D / 4; f += THREADS) {
            int r  = f >> 5;
            int c4 = (f & 31) << 2;
            float4 v = *reinterpret_cast<const float4*>(codebook + (size_t)(cb + r) * D + c4);
            float* dst = cs + r * CS_STRIDE + c4;
            *reinterpret_cast<float2*>(dst)     = make_float2(v.x, v.y);
            *reinterpret_cast<float2*>(dst + 2) = make_float2(v.z, v.w);
        }
        __syncthreads();

        const float* Lb = L + (2 * ty) * L_STRIDE + cb;
        #pragma unroll 8
        for (int cc = 0; cc < CHUNK; cc++) {
            unsigned long long e2[2], b2[4];
            #pragma unroll
            for (int i = 0; i < 2; i++)
                e2[i] = dup2(Lb[i * L_STRIDE + cc]);
            #pragma unroll
            for (int j = 0; j < 4; j++)
                b2[j] = *reinterpret_cast<const unsigned long long*>(cs + cc * CS_STRIDE + 2 * tx + 32 * j);
            #pragma unroll
            for (int i = 0; i < 2; i++)
                #pragma unroll
                for (int j = 0; j < 4; j++)
                    fma2(qa[i][j], e2[i], b2[j]);
        }
    }

    #pragma unroll
    for (int i = 0; i < 2; i++) {
        #pragma unroll
        for (int j = 0; j < 4; j++) {
            float2 p = unpack2(qa[i][j]);
            *reinterpret_cast<float2*>(out_q + (size_t)(row0 + 2 * ty + i) * D + 2 * tx + 32 * j) = p;
        }
    }
}

extern "C" void kernel_launch(void* const* d_in, const int* in_sizes, int n_in,
                              void* d_out, int out_size) {
    const float* x        = (const float*)d_in[0];   // (131072, 128)
    const float* mask     = (const float*)d_in[1];   // (131072,)
    const float* codebook = (const float*)d_in[2];   // (512, 128)
    const float* noise    = (const float*)d_in[3];   // (131072, 512)

    float* out   = (float*)d_out;
    float* out_q = out;                                   // (n, 128)
    float* out_e = out + (size_t)NROWS * D;               // (n, 512)
    float* out_i = out_e + (size_t)NROWS * NC;            // (n,)

    cudaFuncSetAttribute(gumbel_vq_kernel,
                         cudaFuncAttributeMaxDynamicSharedMemorySize, SMEM_BYTES);

    dim3 grid(NROWS / R_TILE);
    gumbel_vq_kernel<<<grid, THREADS, SMEM_BYTES>>>(x, mask, codebook, noise,
                                                    out_q, out_e, out_i);
}

// round 8
// speedup vs baseline: 1.5289x; 1.5289x over previous
#include <cuda_runtime.h>
#include <cuda_fp16.h>
#include <mma.h>
#include <math_constants.h>
#include <cstdint>

using namespace nvcuda;

#define NROWS 131072
#define D     128
#define NC    512

#define MARGIN      1e-3f     // tier-1 gap threshold (f32 accum, f16-input GEMM err ~1e-4 rms)
#define CAND_MARGIN 1.3e-3f   // candidate cut on f16-stored ab (adds f16 rounding slack)

#define AS_LD 136             // halves per row in A/B smem tiles (8-half multiple)
#define CB_LD 132             // floats per row in C smem buffer (4-float multiple)
#define DYN_BYTES (2 * 128 * AS_LD * 2 + 128 * CB_LD * 4)   // 34816*2 + 67584 = 137216

// ---------------- global scratch (static; no allocation) ----------------
__device__ __half g_cf16[NC * D];                  // codebook f16
__device__ __half g_xnh [(size_t)NROWS * D];       // normalized x, f16
__device__ float  g_xn  [(size_t)NROWS * D];       // normalized x, f32 (tier-2)
__device__ __half g_eu  [(size_t)NROWS * NC];      // unnormalized exp (per-chunk max)
__device__ __half g_ab  [(size_t)NROWS * NC];      // ab (f16) for tier-2 candidate scan

// ================= K0: codebook -> f16 =================
__global__ void k0_prep(const float* __restrict__ cb) {
    int i = blockIdx.x * 256 + threadIdx.x;
    if (i < NC * D) g_cf16[i] = __float2half_rn(cb[i]);
}

// ================= K1: normalize x (R3-verified recipe) =================
__global__ void __launch_bounds__(256)
k1_norm(const float* __restrict__ x, const float* __restrict__ mask) {
    int w = threadIdx.x >> 5, lane = threadIdx.x & 31;
    size_t row = (size_t)blockIdx.x * 8 + w;
    float nud = (1.0f - mask[row]) * 1e-6f;
    float4 v = *reinterpret_cast<const float4*>(x + row * D + lane * 4);
    v.x += nud; v.y += nud; v.z += nud; v.w += nud;
    double sq = (double)v.x * v.x + (double)v.y * v.y + (double)v.z * v.z + (double)v.w * v.w;
    #pragma unroll
    for (int d = 1; d <= 16; d <<= 1) sq += __shfl_xor_sync(0xFFFFFFFFu, sq, d);
    float nf = fmaxf((float)sqrt(sq), 1e-6f);
    float4 o;
    o.x = v.x / nf; o.y = v.y / nf; o.z = v.z / nf; o.w = v.w / nf;  // IEEE fp32 div
    *reinterpret_cast<float4*>(&g_xn[row * D + lane * 4]) = o;
    __half2 h01 = __floats2half2_rn(o.x, o.y);
    __half2 h23 = __floats2half2_rn(o.z, o.w);
    uint2 st;
    st.x = *reinterpret_cast<uint32_t*>(&h01);
    st.y = *reinterpret_cast<uint32_t*>(&h23);
    *reinterpret_cast<uint2*>(&g_xnh[row * D + lane * 4]) = st;
}

// ================= K2: WMMA GEMM1 + softmax/argmin + WMMA GEMM2 =================
__global__ void __launch_bounds__(512)
k2_main(const float* __restrict__ codebook, const float* __restrict__ noise,
        float* __restrict__ out_q, float* __restrict__ out_e, float* __restrict__ out_i) {
    extern __shared__ char dyn[];
    __half* As  = reinterpret_cast<__half*>(dyn);
    __half* Bs  = reinterpret_cast<__half*>(dyn + 128 * AS_LD * 2);
    float*  Cbuf = reinterpret_cast<float*>(dyn + 2 * 128 * AS_LD * 2);

    __shared__ float s_m1[128], s_m2[128];
    __shared__ int   s_i1[128];
    __shared__ float s_mc[4][128], s_sc[4][128], s_ci[4][128];
    __shared__ int   s_flag[128];
    __shared__ int   s_cnt;
    __shared__ unsigned long long s_onekey;

    const int t = threadIdx.x, w = t >> 5, lane = t & 31;
    const int row0 = blockIdx.x * 128;
    const int rg = w >> 2, cg = w & 3;    // warp -> 32x32 tile of 128x128

    if (t < 128) { s_m1[t] = -CUDART_INF_F; s_m2[t] = -CUDART_INF_F; s_i1[t] = 1 << 30; }
    if (t == 0) s_cnt = 0;

    // stage A = xn f16 [128][AS_LD]
    for (int idx = t; idx < 8192; idx += 512) {
        int r = idx >> 6, p = idx & 63;
        uint32_t v = reinterpret_cast<const uint32_t*>(g_xnh)[(size_t)(row0 + r) * 64 + p];
        *reinterpret_cast<uint32_t*>(&As[r * AS_LD + 2 * p]) = v;
    }

    // ---------------- GEMM1 + fused per-chunk softmax pass ----------------
    for (int nt = 0; nt < 4; nt++) {
        __syncthreads();   // Bs/Cbuf free
        for (int idx = t; idx < 8192; idx += 512) {
            int r = idx >> 6, p = idx & 63;
            uint32_t v = reinterpret_cast<const uint32_t*>(g_cf16)[(size_t)(nt * 128 + r) * 64 + p];
            *reinterpret_cast<uint32_t*>(&Bs[r * AS_LD + 2 * p]) = v;
        }
        __syncthreads();

        {
            wmma::fragment<wmma::matrix_a, 16, 16, 16, __half, wmma::row_major> af[2];
            wmma::fragment<wmma::matrix_b, 16, 16, 16, __half, wmma::col_major> bf[2];
            wmma::fragment<wmma::accumulator, 16, 16, 16, float> ac[2][2];
            #pragma unroll
            for (int i = 0; i < 2; i++)
                #pragma unroll
                for (int j = 0; j < 2; j++) wmma::fill_fragment(ac[i][j], 0.0f);
            #pragma unroll
            for (int k0 = 0; k0 < 8; k0++) {
                #pragma unroll
                for (int i = 0; i < 2; i++)
                    wmma::load_matrix_sync(af[i], As + (rg * 32 + i * 16) * AS_LD + k0 * 16, AS_LD);
                #pragma unroll
                for (int j = 0; j < 2; j++)
                    wmma::load_matrix_sync(bf[j], Bs + (cg * 32 + j * 16) * AS_LD + k0 * 16, AS_LD);
                #pragma unroll
                for (int i = 0; i < 2; i++)
                    #pragma unroll
                    for (int j = 0; j < 2; j++)
                        wmma::mma_sync(ac[i][j], af[i], bf[j], ac[i][j]);
            }
            #pragma unroll
            for (int i = 0; i < 2; i++)
                #pragma unroll
                for (int j = 0; j < 2; j++)
                    wmma::store_matrix_sync(Cbuf + (rg * 32 + i * 16) * CB_LD + cg * 32 + j * 16,
                                            ac[i][j], CB_LD, wmma::mem_row_major);
        }
        __syncthreads();

        // fused pass: warp w owns rows 8w..8w+7
        for (int rr8 = 0; rr8 < 8; rr8++) {
            int rr = w * 8 + rr8;
            size_t go = (size_t)(row0 + rr) * NC + nt * 128;
            float ab[4], v[4];
            float mc = -CUDART_INF_F;
            #pragma unroll
            for (int i = 0; i < 4; i++) {
                ab[i] = Cbuf[rr * CB_LD + lane + 32 * i];
                v[i]  = 2.0f * ab[i] + noise[go + lane + 32 * i];
                mc = fmaxf(mc, v[i]);
                g_ab[go + lane + 32 * i] = __float2half_rn(ab[i]);
            }
            // lane-local top-2 of ab
            float lm1 = -CUDART_INF_F, lm2 = -CUDART_INF_F;
            int li = 1 << 30;
            #pragma unroll
            for (int i = 0; i < 4; i++) {
                int ci = nt * 128 + lane + 32 * i;
                if (ab[i] > lm1) { lm2 = lm1; lm1 = ab[i]; li = ci; }
                else             { lm2 = fmaxf(lm2, ab[i]); }
            }
            // warp butterfly: chunk max + top-2 merge
            #pragma unroll
            for (int d2 = 1; d2 <= 16; d2 <<= 1) {
                mc = fmaxf(mc, __shfl_xor_sync(0xFFFFFFFFu, mc, d2));
                float om1 = __shfl_xor_sync(0xFFFFFFFFu, lm1, d2);
                float om2 = __shfl_xor_sync(0xFFFFFFFFu, lm2, d2);
                int   oi  = __shfl_xor_sync(0xFFFFFFFFu, li,  d2);
                if (om1 > lm1)       { lm2 = fmaxf(lm1, om2); lm1 = om1; li = oi; }
                else if (om1 == lm1) { lm2 = lm1; li = min(li, oi); }
                else                 { lm2 = fmaxf(lm2, om1); }
            }
            if (lane == 0) {
                float gm1 = s_m1[rr], gm2 = s_m2[rr];
                int gi = s_i1[rr];
                if (lm1 > gm1)       { gm2 = fmaxf(gm1, lm2); gm1 = lm1; gi = li; }
                else if (lm1 == gm1) { gm2 = gm1; gi = min(gi, li); }
                else                 { gm2 = fmaxf(gm2, lm1); }
                s_m1[rr] = gm1; s_m2[rr] = gm2; s_i1[rr] = gi;
                s_mc[nt][rr] = mc;
            }
            // exp with chunk max; write eu f16
            float sum = 0.f;
            #pragma unroll
            for (int i = 0; i < 4; i++) {
                float e = __expf(v[i] - mc);
                sum += e;
                g_eu[go + lane + 32 * i] = __float2half_rn(e);
            }
            #pragma unroll
            for (int d2 = 1; d2 <= 16; d2 <<= 1)
                sum += __shfl_xor_sync(0xFFFFFFFFu, sum, d2);
            if (lane == 0) s_sc[nt][rr] = sum;
        }
    }
    __syncthreads();

    // ---------------- finalize per row ----------------
    if (t < 128) {
        float mc0 = s_mc[0][t], mc1 = s_mc[1][t], mc2 = s_mc[2][t], mc3 = s_mc[3][t];
        float m = fmaxf(fmaxf(mc0, mc1), fmaxf(mc2, mc3));
        float w0 = __expf(mc0 - m), w1 = __expf(mc1 - m),
              w2 = __expf(mc2 - m), w3 = __expf(mc3 - m);
        float s = s_sc[0][t] * w0 + s_sc[1][t] * w1 + s_sc[2][t] * w2 + s_sc[3][t] * w3;
        float inv = 1.0f / s;
        s_ci[0][t] = w0 * inv; s_ci[1][t] = w1 * inv;
        s_ci[2][t] = w2 * inv; s_ci[3][t] = w3 * inv;
        if (s_m1[t] - s_m2[t] > MARGIN) out_i[row0 + t] = (float)s_i1[t];
        else { int p = atomicAdd(&s_cnt, 1); s_flag[p] = t; }
    }
    __syncthreads();

    // ---------------- tier-2: exact reference argmin for flagged rows ----------------
    {
        int cnt = s_cnt;
        for (int f = 0; f < cnt; f++) {
            int rr = s_flag[f];
            int grr = row0 + rr;
            if (t == 0) s_onekey = ~0ull;
            __syncthreads();
            float abf = __half2float(g_ab[(size_t)grr * NC + t]);
            if (abf >= s_m1[rr] - CAND_MARGIN) {
                const float* xr = g_xn + (size_t)grr * D;
                const float* cj = codebook + (size_t)t * D;
                float acc = 0.0f;
                #pragma unroll 8
                for (int k = 0; k < 128; k++)
                    acc = fmaf(xr[k], cj[k], acc);      // serial ascending k (matches ref)
                float df = (1.0f - 2.0f * acc) + 1.0f;
                unsigned long long key =
                    ((unsigned long long)__float_as_uint(df) << 32) | (unsigned)t;
                atomicMin(&s_onekey, key);
            }
            __syncthreads();
            if (t == 0) out_i[grr] = (float)(unsigned)(s_onekey & 0xffffffffu);
        }
    }

    // ---------------- GEMM2: quantized = e @ C (accumulate over 4 K-chunks) ----------------
    wmma::fragment<wmma::accumulator, 16, 16, 16, float> ac2[2][2];
    #pragma unroll
    for (int i = 0; i < 2; i++)
        #pragma unroll
        for (int j = 0; j < 2; j++) wmma::fill_fragment(ac2[i][j], 0.0f);

    for (int kc = 0; kc < 4; kc++) {
        __syncthreads();
        for (int idx = t; idx < 8192; idx += 512) {
            int r = idx >> 6, p = idx & 63;
            uint32_t packed = reinterpret_cast<const uint32_t*>(g_eu)[(size_t)(row0 + r) * 256 + kc * 64 + p];
            __half2 h = *reinterpret_cast<__half2*>(&packed);
            float ci = s_ci[kc][r];
            float f0 = __half2float(h.x) * ci;
            float f1 = __half2float(h.y) * ci;
            *reinterpret_cast<float2*>(out_e + (size_t)(row0 + r) * NC + kc * 128 + 2 * p) =
                make_float2(f0, f1);
            __half2 ho = __floats2half2_rn(f0, f1);
            *reinterpret_cast<uint32_t*>(&As[r * AS_LD + 2 * p]) = *reinterpret_cast<uint32_t*>(&ho);
            uint32_t bv = reinterpret_cast<const uint32_t*>(g_cf16)[(size_t)(kc * 128 + r) * 64 + p];
            *reinterpret_cast<uint32_t*>(&Bs[r * AS_LD + 2 * p]) = bv;
        }
        __syncthreads();
        {
            wmma::fragment<wmma::matrix_a, 16, 16, 16, __half, wmma::row_major> af[2];
            wmma::fragment<wmma::matrix_b, 16, 16, 16, __half, wmma::row_major> bf[2];
            #pragma unroll
            for (int k0 = 0; k0 < 8; k0++) {
                #pragma unroll
                for (int i = 0; i < 2; i++)
                    wmma::load_matrix_sync(af[i], As + (rg * 32 + i * 16) * AS_LD + k0 * 16, AS_LD);
                #pragma unroll
                for (int j = 0; j < 2; j++)
                    wmma::load_matrix_sync(bf[j], Bs + (k0 * 16) * AS_LD + cg * 32 + j * 16, AS_LD);
                #pragma unroll
                for (int i = 0; i < 2; i++)
                    #pragma unroll
                    for (int j = 0; j < 2; j++)
                        wmma::mma_sync(ac2[i][j], af[i], bf[j], ac2[i][j]);
            }
        }
    }
    __syncthreads();
    #pragma unroll
    for (int i = 0; i < 2; i++)
        #pragma unroll
        for (int j = 0; j < 2; j++)
            wmma::store_matrix_sync(Cbuf + (rg * 32 + i * 16) * CB_LD + cg * 32 + j * 16,
                                    ac2[i][j], CB_LD, wmma::mem_row_major);
    __syncthreads();
    {
        int r = t >> 2, q = t & 3;
        #pragma unroll
        for (int i = 0; i < 8; i++) {
            int c = q * 32 + i * 4;
            float4 o = *reinterpret_cast<float4*>(&Cbuf[r * CB_LD + c]);
            *reinterpret_cast<float4*>(out_q + (size_t)(row0 + r) * D + c) = o;
        }
    }
}

extern "C" void kernel_launch(void* const* d_in, const int* in_sizes, int n_in,
                              void* d_out, int out_size) {
    const float* x        = (const float*)d_in[0];
    const float* mask     = (const float*)d_in[1];
    const float* codebook = (const float*)d_in[2];
    const float* noise    = (const float*)d_in[3];

    float* out   = (float*)d_out;
    float* out_q = out;
    float* out_e = out + (size_t)NROWS * D;
    float* out_i = out_e + (size_t)NROWS * NC;

    cudaFuncSetAttribute(k2_main, cudaFuncAttributeMaxDynamicSharedMemorySize, DYN_BYTES);

    k0_prep<<<(NC * D + 255) / 256, 256>>>(codebook);
    k1_norm<<<NROWS / 8, 256>>>(x, mask);
    k2_main<<<NROWS / 128, 512, DYN_BYTES>>>(codebook, noise, out_q, out_e, out_i);
}